// round 7
// baseline (speedup 1.0000x reference)
#include <cuda_runtime.h>
#include <cuda_fp16.h>
#include <cstdint>

// Problem sizes (fixed by the reference)
#define M_ROWS 8192
#define IN_F   512
#define OUT_F  512
#define KDIM   (IN_F * 8)    // 4096 (permuted per-feature: evens then odds)
#define KCMP   (KDIM / 2)    // 2048 compressed K

// ---------------------------------------------------------------------------
// Device scratch (allocation-free rule: __device__ globals)
// ---------------------------------------------------------------------------
__device__ __align__(16) __half   g_Ac[(size_t)M_ROWS * KCMP];     // 32 MB compressed bases
__device__ __align__(16) __half   g_Wh[(size_t)OUT_F * KDIM];      //  4 MB permuted coeffs
__device__ __align__(16) uint32_t g_meta[(size_t)M_ROWS * (KDIM / 32)]; // 4 MB 2:4 metadata

// ---------------------------------------------------------------------------
// Kernel 1: bases -> compressed 2:4 A + metadata.
// Per feature: weights w0..w3 at slots j0..j0+3. K' = [0,2,4,6,1,3,5,7].
// Even group holds (w0,w2) if j0 even else (w1,w3); odd group the other pair.
// meta byte LUT by j0: {0x44,0x49,0x99,0x9E,0xEE}.
// ---------------------------------------------------------------------------
__device__ __forceinline__ void basis_eval(float xv, float g0, float invh,
                                           uint32_t& p0, uint32_t& p1, uint32_t& mb) {
    float e  = __expf(2.0f * xv);
    float xn = 1.0f - 2.0f / (e + 1.0f);   // tanh(xv)

    float t  = (xn - g0) * invh;
    int   m  = (int)floorf(t);
    m = min(max(m, 3), 7);
    float u  = t - (float)m;

    float um = 1.0f - u;
    float u2 = u * u, u3 = u2 * u;
    const float s = 1.0f / 6.0f;
    float w0 = um * um * um * s;
    float w1 = (3.0f * u3 - 6.0f * u2 + 4.0f) * s;
    float w2 = (-3.0f * u3 + 3.0f * u2 + 3.0f * u + 1.0f) * s;
    float w3 = u3 * s;
    int j0 = m - 3;                        // in [0,4]

    __half2 P = __floats2half2_rn(w0, w2);
    __half2 Q = __floats2half2_rn(w1, w3);
    uint32_t uP = *(uint32_t*)&P;
    uint32_t uQ = *(uint32_t*)&Q;
    bool odd = (j0 & 1);
    p0 = odd ? uQ : uP;                    // even-group pair
    p1 = odd ? uP : uQ;                    // odd-group pair
    mb = (uint32_t)((0xEE9E994944ull >> (8 * j0)) & 0xFFu);
}

__global__ void basis_kernel(const float* __restrict__ x,
                             const float* __restrict__ grid) {
    int p = blockIdx.x * blockDim.x + threadIdx.x;
    if (p >= M_ROWS * IN_F / 2) return;

    float g0   = __ldg(grid);
    float invh = 1.0f / (__ldg(grid + 1) - g0);

    float2 xv = reinterpret_cast<const float2*>(x)[p];
    uint32_t a0, a1, m0, b0, b1, m1;
    basis_eval(xv.x, g0, invh, a0, a1, m0);
    basis_eval(xv.y, g0, invh, b0, b1, m1);

    // compressed A: 8 halves (two features x 4) at halves offset p*8
    *reinterpret_cast<uint4*>(g_Ac + (size_t)p * 8) = make_uint4(a0, a1, b0, b1);
    // metadata: uint16 index == p  (layout [row][chunk] uint32, halves by pair)
    reinterpret_cast<uint16_t*>(g_meta)[p] = (uint16_t)(m0 | (m1 << 8));
}

// ---------------------------------------------------------------------------
// Kernel 2: pack W'[o][i*8+kp] = C[i][o][perm[kp]], perm = [0,2,4,6,1,3,5,7].
// ---------------------------------------------------------------------------
__global__ void wpack_kernel(const float* __restrict__ coef) {
    int t = blockIdx.x * blockDim.x + threadIdx.x;
    if (t >= IN_F * OUT_F) return;
    int i = t & (IN_F - 1);
    int o = t >> 9;

    const float4* src = reinterpret_cast<const float4*>(coef + ((size_t)i * OUT_F + o) * 8);
    float4 c0 = __ldg(src);      // k 0..3
    float4 c1 = __ldg(src + 1);  // k 4..7

    __half2 h0 = __floats2half2_rn(c0.x, c0.z);  // k 0,2
    __half2 h1 = __floats2half2_rn(c1.x, c1.z);  // k 4,6
    __half2 h2 = __floats2half2_rn(c0.y, c0.w);  // k 1,3
    __half2 h3 = __floats2half2_rn(c1.y, c1.w);  // k 5,7
    *reinterpret_cast<uint4*>(g_Wh + (size_t)o * KDIM + i * 8) =
        make_uint4(*(uint32_t*)&h0, *(uint32_t*)&h1, *(uint32_t*)&h2, *(uint32_t*)&h3);
}

// ---------------------------------------------------------------------------
// Kernel 3: sparse GEMM via mma.sp m16n8k32 (2:4), fp16 -> fp32.
// CTA 224x128 (M padded to 8288), grid (4,37) = 148 CTAs = one wave.
// 8 warps 2x4, warp tile 112x32. 3-stage cp.async.
// ---------------------------------------------------------------------------
#define BM 224
#define BN 128
#define ROWA 24                        // compressed row stride (halves), 48B: LDSM conflict-free
#define ROWB 40                        // B row stride (halves), 80B
#define STAGES 3
#define KT (KDIM / 32)                 // 128 chunks of k32 (16 compressed)
#define A_ST (BM * ROWA)               // halves
#define B_ST (BN * ROWB)               // halves
#define MET_ST BM                      // uint32 per stage
#define A_BYTES (STAGES * A_ST * 2)
#define B_BYTES (STAGES * B_ST * 2)
#define MET_BYTES (STAGES * MET_ST * 4)
#define SMEM_BYTES (A_BYTES + B_BYTES + MET_BYTES)

__device__ __forceinline__ void cp16(void* smem, const void* gmem) {
    uint32_t sa = (uint32_t)__cvta_generic_to_shared(smem);
    asm volatile("cp.async.cg.shared.global [%0], [%1], 16;\n" :: "r"(sa), "l"(gmem));
}
__device__ __forceinline__ void cp4(void* smem, const void* gmem) {
    uint32_t sa = (uint32_t)__cvta_generic_to_shared(smem);
    asm volatile("cp.async.ca.shared.global [%0], [%1], 4;\n" :: "r"(sa), "l"(gmem));
}
__device__ __forceinline__ void ldsm_x4(uint32_t (&r)[4], uint32_t saddr) {
    asm volatile("ldmatrix.sync.aligned.m8n8.x4.shared.b16 {%0,%1,%2,%3}, [%4];"
                 : "=r"(r[0]), "=r"(r[1]), "=r"(r[2]), "=r"(r[3]) : "r"(saddr));
}
__device__ __forceinline__ void mma_sp(float (&d)[4], const uint32_t (&a)[4],
                                       const uint32_t (&b)[4], uint32_t e) {
    asm volatile(
        "mma.sp.sync.aligned.m16n8k32.row.col.f32.f16.f16.f32 "
        "{%0,%1,%2,%3}, {%4,%5,%6,%7}, {%8,%9,%10,%11}, {%0,%1,%2,%3}, %12, 0x0;"
        : "+f"(d[0]), "+f"(d[1]), "+f"(d[2]), "+f"(d[3])
        : "r"(a[0]), "r"(a[1]), "r"(a[2]), "r"(a[3]),
          "r"(b[0]), "r"(b[1]), "r"(b[2]), "r"(b[3]), "r"(e));
}

__global__ void __launch_bounds__(256, 1) gemm_kernel(float* __restrict__ C) {
    extern __shared__ __half sm[];
    __half* AsBase = sm;                                  // [STAGES][BM][ROWA]
    __half* BsBase = sm + STAGES * A_ST;                  // [STAGES][BN][ROWB]
    uint32_t* MetBase = reinterpret_cast<uint32_t*>(sm + STAGES * (A_ST + B_ST));
    const uint32_t smem0 = (uint32_t)__cvta_generic_to_shared(sm);
    const uint32_t Bs0   = smem0 + A_BYTES;

    const int tid  = threadIdx.x;
    const int bm   = blockIdx.y * BM;
    const int bn   = blockIdx.x * BN;
    const int wid  = tid >> 5;
    const int lane = tid & 31;
    const int wm   = (wid >> 2) * 112;   // 0 / 112
    const int wn   = (wid & 3) * 32;     // 0..96
    const int gID  = lane >> 2;
    const int tg   = lane & 3;
    const int lrow = lane & 15;
    const int lcol = (lane >> 4) << 3;
    const uint32_t psel = (lane & 1) ? 0x7632u : 0x5410u;  // k-half select for meta

    float acc[7][4][4];
#pragma unroll
    for (int a = 0; a < 7; ++a)
#pragma unroll
        for (int b = 0; b < 4; ++b)
#pragma unroll
            for (int c = 0; c < 4; ++c) acc[a][b][c] = 0.0f;

    auto issue = [&](int s, int kc) {
        __half* As = AsBase + s * A_ST;
        __half* Bs = BsBase + s * B_ST;
        uint32_t* Ms = MetBase + s * MET_ST;
        // A compressed: 224 rows x 2 16B-chunks = 448
#pragma unroll
        for (int i = 0; i < 2; ++i) {
            int id = tid + 256 * i;
            if (id < BM * 2) {
                int r = id >> 1, c = id & 1;
                int gr = min(bm + r, M_ROWS - 1);
                cp16(As + r * ROWA + c * 8, g_Ac + (size_t)gr * KCMP + kc * 16 + c * 8);
            }
        }
        // B: 128 rows x 4 16B-chunks = 512
#pragma unroll
        for (int i = 0; i < 2; ++i) {
            int id = tid + 256 * i;
            int r = id >> 2, c = id & 3;
            cp16(Bs + r * ROWB + c * 8, g_Wh + (size_t)(bn + r) * KDIM + kc * 32 + c * 8);
        }
        // metadata: 224 words
        if (tid < BM) {
            int gr = min(bm + tid, M_ROWS - 1);
            cp4(Ms + tid, g_meta + (size_t)gr * KT + kc);
        }
        asm volatile("cp.async.commit_group;\n");
    };

    issue(0, 0);
    issue(1, 1);

    for (int kc = 0; kc < KT; ++kc) {
        if (kc < KT - 1) {
            asm volatile("cp.async.wait_group 1;\n");
        } else {
            asm volatile("cp.async.wait_group 0;\n");
        }
        __syncthreads();

        if (kc + 2 < KT) issue((kc + 2) % STAGES, kc + 2);

        const int s = kc % STAGES;
        const uint32_t As_u = smem0 + (s * A_ST) * 2;
        const uint32_t Bs_u = Bs0 + (s * B_ST) * 2;
        const uint32_t* Ms  = MetBase + s * MET_ST;

        // A fragments (compressed 16 cols) + metadata per m-tile
        uint32_t af[7][4], E[7];
#pragma unroll
        for (int mt = 0; mt < 7; ++mt) {
            ldsm_x4(af[mt], As_u + ((wm + mt * 16 + lrow) * ROWA + lcol) * 2);
            uint32_t lo = Ms[wm + mt * 16 + gID];
            uint32_t hi = Ms[wm + mt * 16 + gID + 8];
            E[mt] = __byte_perm(lo, hi, psel);
        }
        // B fragments: k0..15 and k16..31
        uint32_t bf[4][4];
#pragma unroll
        for (int j = 0; j < 2; ++j) {
            uint32_t rA[4], rB[4];
            ldsm_x4(rA, Bs_u + ((wn + j * 16 + lrow) * ROWB + 0  + lcol) * 2);
            ldsm_x4(rB, Bs_u + ((wn + j * 16 + lrow) * ROWB + 16 + lcol) * 2);
            bf[2 * j][0] = rA[0]; bf[2 * j][1] = rA[2]; bf[2 * j][2] = rB[0]; bf[2 * j][3] = rB[2];
            bf[2 * j + 1][0] = rA[1]; bf[2 * j + 1][1] = rA[3];
            bf[2 * j + 1][2] = rB[1]; bf[2 * j + 1][3] = rB[3];
        }
#pragma unroll
        for (int mt = 0; mt < 7; ++mt)
#pragma unroll
            for (int nt = 0; nt < 4; ++nt)
                mma_sp(acc[mt][nt], af[mt], bf[nt], E[mt]);

        __syncthreads();
    }

    // Epilogue: guarded fp32 stores (padded M rows skipped).
#pragma unroll
    for (int mt = 0; mt < 7; ++mt) {
        int r0 = bm + wm + mt * 16 + gID;
#pragma unroll
        for (int nt = 0; nt < 4; ++nt) {
            int c = bn + wn + nt * 8 + tg * 2;
            if (r0 < M_ROWS)
                *reinterpret_cast<float2*>(C + (size_t)r0 * OUT_F + c) =
                    make_float2(acc[mt][nt][0], acc[mt][nt][1]);
            if (r0 + 8 < M_ROWS)
                *reinterpret_cast<float2*>(C + (size_t)(r0 + 8) * OUT_F + c) =
                    make_float2(acc[mt][nt][2], acc[mt][nt][3]);
        }
    }
}

// ---------------------------------------------------------------------------
extern "C" void kernel_launch(void* const* d_in, const int* in_sizes, int n_in,
                              void* d_out, int out_size) {
    const float* x    = (const float*)d_in[0];
    const float* coef = (const float*)d_in[1];
    const float* grid = (const float*)d_in[2];
    float* out = (float*)d_out;

    basis_kernel<<<(M_ROWS * IN_F / 2 + 255) / 256, 256>>>(x, grid);
    wpack_kernel<<<(IN_F * OUT_F + 255) / 256, 256>>>(coef);

    static int smem_set = 0;
    if (!smem_set) {
        cudaFuncSetAttribute(gemm_kernel, cudaFuncAttributeMaxDynamicSharedMemorySize,
                             SMEM_BYTES);
        smem_set = 1;
    }
    dim3 g(OUT_F / BN, 37);   // 4 x 37 = 148 CTAs = one full wave
    gemm_kernel<<<g, 256, SMEM_BYTES>>>(out);
}

// round 8
// speedup vs baseline: 3.4431x; 3.4431x over previous
#include <cuda_runtime.h>
#include <cuda_fp16.h>
#include <cstdint>

// Problem sizes (fixed by the reference)
#define M_ROWS 8192
#define IN_F   512
#define OUT_F  512
#define KDIM   (IN_F * 8)   // 4096

// ---------------------------------------------------------------------------
// Device scratch (allocation-free rule: __device__ globals)
// ---------------------------------------------------------------------------
__device__ __align__(16) float  g_xT[(size_t)IN_F * M_ROWS];   // 16 MB x^T
__device__ __align__(16) __half g_Wh[(size_t)OUT_F * KDIM];    //  4 MB packed coeffs

// ---------------------------------------------------------------------------
// Kernel 1: transpose x -> xT[feat][row]  (coalesced feeds for fused GEMM)
// ---------------------------------------------------------------------------
__global__ void xpose_kernel(const float* __restrict__ x) {
    __shared__ float tile[32][33];
    int bf = blockIdx.x * 32;   // feature
    int br = blockIdx.y * 32;   // row
    int tx = threadIdx.x, ty = threadIdx.y;
#pragma unroll
    for (int i = 0; i < 4; ++i)
        tile[ty + 8 * i][tx] = x[(size_t)(br + ty + 8 * i) * IN_F + bf + tx];
    __syncthreads();
#pragma unroll
    for (int i = 0; i < 4; ++i)
        g_xT[(size_t)(bf + ty + 8 * i) * M_ROWS + br + tx] = tile[tx][ty + 8 * i];
}

// ---------------------------------------------------------------------------
// Kernel 2: pack W[o][i*8+k] = C[i][o][k], fp16.
// ---------------------------------------------------------------------------
__global__ void wpack_kernel(const float* __restrict__ coef) {
    int t = blockIdx.x * blockDim.x + threadIdx.x;
    if (t >= IN_F * OUT_F) return;
    int i = t & (IN_F - 1);
    int o = t >> 9;

    const float4* src = reinterpret_cast<const float4*>(coef + ((size_t)i * OUT_F + o) * 8);
    float4 c0 = __ldg(src);
    float4 c1 = __ldg(src + 1);

    __half2 h0 = __floats2half2_rn(c0.x, c0.y);
    __half2 h1 = __floats2half2_rn(c0.z, c0.w);
    __half2 h2 = __floats2half2_rn(c1.x, c1.y);
    __half2 h3 = __floats2half2_rn(c1.z, c1.w);
    *reinterpret_cast<uint4*>(g_Wh + (size_t)o * KDIM + i * 8) =
        make_uint4(*(uint32_t*)&h0, *(uint32_t*)&h1, *(uint32_t*)&h2, *(uint32_t*)&h3);
}

// ---------------------------------------------------------------------------
// Basis evaluation: uniform cubic B-spline, funnel-shift placement (8 halves).
// ---------------------------------------------------------------------------
__device__ __forceinline__ uint4 basis_eval(float xv, float g0, float invh) {
    float e  = __expf(2.0f * xv);
    float xn = 1.0f - 2.0f / (e + 1.0f);   // tanh(xv)

    float t  = (xn - g0) * invh;
    int   m  = (int)floorf(t);
    m = min(max(m, 3), 7);
    float u  = t - (float)m;

    float um = 1.0f - u;
    float u2 = u * u, u3 = u2 * u;
    const float s = 1.0f / 6.0f;
    float w0 = um * um * um * s;
    float w1 = (3.0f * u3 - 6.0f * u2 + 4.0f) * s;
    float w2 = (-3.0f * u3 + 3.0f * u2 + 3.0f * u + 1.0f) * s;
    float w3 = u3 * s;
    int j0 = m - 3;

    __half2 hA = __floats2half2_rn(w0, w1);
    __half2 hB = __floats2half2_rn(w2, w3);
    uint32_t u0 = *(uint32_t*)&hA;
    uint32_t u1 = *(uint32_t*)&hB;

    uint32_t b  = (j0 & 1) << 4;
    uint32_t t0 = u0 << b;
    uint32_t t1 = __funnelshift_l(u0, u1, b);
    uint32_t t2 = __funnelshift_l(u1, 0u, b);
    int ws = j0 >> 1;

    uint4 o;
    o.x = (ws == 0) ? t0 : 0u;
    o.y = (ws == 0) ? t1 : ((ws == 1) ? t0 : 0u);
    o.z = (ws == 0) ? t2 : ((ws == 1) ? t1 : t0);
    o.w = (ws == 1) ? t2 : ((ws == 2) ? t1 : 0u);
    return o;
}

// ---------------------------------------------------------------------------
// Kernel 3: FUSED basis + GEMM.  out = A @ W^T, A generated in-CTA.
// CTA 224x128 (M padded to 8288), grid (4,37) = 148 CTAs = one wave.
// 8 warps 2x4, warp tile 112x32. 3-stage smem ring; B via cp.async,
// A computed (tanh+spline) and STS'd per chunk, x loads software-pipelined.
// ---------------------------------------------------------------------------
#define BM 224
#define BN 128
#define BK 32                          // halves per K chunk = 4 features
#define ROWH 40
#define STAGES 3
#define KT (KDIM / BK)                 // 128
#define A_ST (BM * ROWH)
#define B_ST (BN * ROWH)
#define SMEM_BYTES (STAGES * (A_ST + B_ST) * 2)   // 84480

__device__ __forceinline__ void cp16(void* smem, const void* gmem) {
    uint32_t sa = (uint32_t)__cvta_generic_to_shared(smem);
    asm volatile("cp.async.cg.shared.global [%0], [%1], 16;\n" :: "r"(sa), "l"(gmem));
}
__device__ __forceinline__ void ldsm_x4(uint32_t (&r)[4], uint32_t saddr) {
    asm volatile("ldmatrix.sync.aligned.m8n8.x4.shared.b16 {%0,%1,%2,%3}, [%4];"
                 : "=r"(r[0]), "=r"(r[1]), "=r"(r[2]), "=r"(r[3]) : "r"(saddr));
}
__device__ __forceinline__ void mma_f16(float (&d)[4], uint32_t a0, uint32_t a1,
                                        uint32_t a2, uint32_t a3,
                                        uint32_t b0, uint32_t b1) {
    asm volatile(
        "mma.sync.aligned.m16n8k16.row.col.f32.f16.f16.f32 "
        "{%0,%1,%2,%3}, {%4,%5,%6,%7}, {%8,%9}, {%0,%1,%2,%3};"
        : "+f"(d[0]), "+f"(d[1]), "+f"(d[2]), "+f"(d[3])
        : "r"(a0), "r"(a1), "r"(a2), "r"(a3), "r"(b0), "r"(b1));
}

__global__ void __launch_bounds__(256, 1) gemm_kernel(float* __restrict__ C,
                                                      const float* __restrict__ grid) {
    extern __shared__ __half sm[];
    __half* AsBase = sm;
    __half* BsBase = sm + STAGES * A_ST;
    const uint32_t smem0 = (uint32_t)__cvta_generic_to_shared(sm);
    const uint32_t Bs0   = smem0 + STAGES * A_ST * 2;

    const int tid  = threadIdx.x;
    const int bm   = blockIdx.y * BM;
    const int bn   = blockIdx.x * BN;
    const int wid  = tid >> 5;
    const int lane = tid & 31;
    const int wm   = (wid >> 2) * 112;
    const int wn   = (wid & 3) * 32;
    const int gID  = lane >> 2;
    const int tg   = lane & 3;
    const int lrow = lane & 15;
    const int lcol = (lane >> 4) << 3;

    const float g0   = __ldg(grid);
    const float invh = 1.0f / (__ldg(grid + 1) - g0);

    // per-thread A-gen assignment: elements e = tid + 256*i, e < 896
    int arow[4], gr_[4];
    uint32_t fi_[4];
#pragma unroll
    for (int i = 0; i < 4; ++i) {
        int e = tid + 256 * i;
        arow[i] = e >> 2;
        fi_[i]  = e & 3;
        gr_[i]  = min(bm + arow[i], M_ROWS - 1);
    }
    const bool has4 = (tid < 128);   // e=tid+768 < 896 iff tid<128

    float acc[7][4][4];
#pragma unroll
    for (int a = 0; a < 7; ++a)
#pragma unroll
        for (int b = 0; b < 4; ++b)
#pragma unroll
            for (int c = 0; c < 4; ++c) acc[a][b][c] = 0.0f;

    auto issueB = [&](int s, int kc) {
        __half* Bs = BsBase + s * B_ST;
#pragma unroll
        for (int i = 0; i < 2; ++i) {
            int id = tid + 256 * i;
            int r = id >> 2, c = id & 3;
            cp16(Bs + r * ROWH + c * 8, g_Wh + (size_t)(bn + r) * KDIM + kc * BK + c * 8);
        }
        asm volatile("cp.async.commit_group;\n");
    };

    auto load_xv = [&](int kc, float (&xv)[4]) {
        int f0 = kc * 4;
#pragma unroll
        for (int i = 0; i < 4; ++i) {
            if (i < 3 || has4)
                xv[i] = __ldg(g_xT + (size_t)(f0 + fi_[i]) * M_ROWS + gr_[i]);
        }
    };

    auto gen_a = [&](int s, const float (&xv)[4]) {
        __half* As = AsBase + s * A_ST;
#pragma unroll
        for (int i = 0; i < 4; ++i) {
            if (i < 3 || has4) {
                uint4 o = basis_eval(xv[i], g0, invh);
                *reinterpret_cast<uint4*>(As + arow[i] * ROWH + fi_[i] * 8) = o;
            }
        }
    };

    // prologue: A for chunks 0,1 + B for chunks 0,1; preload x for chunk 2
    float xva[4];
    load_xv(0, xva); gen_a(0, xva);
    load_xv(1, xva); gen_a(1, xva);
    issueB(0, 0);
    issueB(1, 1);
    load_xv(2, xva);

    for (int kc = 0; kc < KT; ++kc) {
        if (kc < KT - 1) {
            asm volatile("cp.async.wait_group 1;\n");
        } else {
            asm volatile("cp.async.wait_group 0;\n");
        }
        __syncthreads();

        const int s2 = (kc + 2) % STAGES;
        if (kc + 2 < KT) issueB(s2, kc + 2);

        const int s = kc % STAGES;
        const uint32_t As_u = smem0 + (s * A_ST) * 2;
        const uint32_t Bs_u = Bs0 + (s * B_ST) * 2;

#pragma unroll
        for (int ks = 0; ks < BK; ks += 16) {
            uint32_t af[7][4];
#pragma unroll
            for (int mt = 0; mt < 7; ++mt)
                ldsm_x4(af[mt], As_u + ((wm + mt * 16 + lrow) * ROWH + ks + lcol) * 2);
            uint32_t bf[4][2];
#pragma unroll
            for (int j = 0; j < 2; ++j) {
                uint32_t r[4];
                ldsm_x4(r, Bs_u + ((wn + j * 16 + lrow) * ROWH + ks + lcol) * 2);
                bf[2 * j][0] = r[0]; bf[2 * j + 1][0] = r[1];
                bf[2 * j][1] = r[2]; bf[2 * j + 1][1] = r[3];
            }
#pragma unroll
            for (int mt = 0; mt < 7; ++mt)
#pragma unroll
                for (int nt = 0; nt < 4; ++nt)
                    mma_f16(acc[mt][nt], af[mt][0], af[mt][1], af[mt][2], af[mt][3],
                            bf[nt][0], bf[nt][1]);
        }

        // generate A for chunk kc+2 (x values preloaded before the MMA block)
        if (kc + 2 < KT) {
            gen_a(s2, xva);
            if (kc + 3 < KT) load_xv(kc + 3, xva);
        }
        __syncthreads();
    }

    // Epilogue: guarded fp32 stores (padded M rows skipped).
#pragma unroll
    for (int mt = 0; mt < 7; ++mt) {
        int r0 = bm + wm + mt * 16 + gID;
#pragma unroll
        for (int nt = 0; nt < 4; ++nt) {
            int c = bn + wn + nt * 8 + tg * 2;
            if (r0 < M_ROWS)
                *reinterpret_cast<float2*>(C + (size_t)r0 * OUT_F + c) =
                    make_float2(acc[mt][nt][0], acc[mt][nt][1]);
            if (r0 + 8 < M_ROWS)
                *reinterpret_cast<float2*>(C + (size_t)(r0 + 8) * OUT_F + c) =
                    make_float2(acc[mt][nt][2], acc[mt][nt][3]);
        }
    }
}

// ---------------------------------------------------------------------------
extern "C" void kernel_launch(void* const* d_in, const int* in_sizes, int n_in,
                              void* d_out, int out_size) {
    const float* x    = (const float*)d_in[0];
    const float* coef = (const float*)d_in[1];
    const float* grid = (const float*)d_in[2];
    float* out = (float*)d_out;

    dim3 tb(32, 8);
    dim3 tg_(IN_F / 32, M_ROWS / 32);
    xpose_kernel<<<tg_, tb>>>(x);
    wpack_kernel<<<(IN_F * OUT_F + 255) / 256, 256>>>(coef);

    static int smem_set = 0;
    if (!smem_set) {
        cudaFuncSetAttribute(gemm_kernel, cudaFuncAttributeMaxDynamicSharedMemorySize,
                             SMEM_BYTES);
        smem_set = 1;
    }
    dim3 g(OUT_F / BN, 37);   // 4 x 37 = 148 CTAs = one full wave
    gemm_kernel<<<g, 256, SMEM_BYTES>>>(out, grid);
}

// round 9
// speedup vs baseline: 4.0814x; 1.1854x over previous
#include <cuda_runtime.h>
#include <cuda_fp16.h>
#include <cstdint>

// Problem sizes (fixed by the reference)
#define M_ROWS 8192
#define IN_F   512
#define OUT_F  512
#define KDIM   (IN_F * 8)   // 4096

// ---------------------------------------------------------------------------
// Device scratch (allocation-free rule: __device__ globals)
// ---------------------------------------------------------------------------
__device__ __align__(16) __half g_Ah[(size_t)M_ROWS * KDIM]; // 64 MB bases (fp16)
__device__ __align__(16) __half g_Wh[(size_t)OUT_F * KDIM];  //  4 MB packed coeffs

// ---------------------------------------------------------------------------
// Kernel 1: bases, 4 independent elements/thread (MUFU-chain ILP).
// ---------------------------------------------------------------------------
__device__ __forceinline__ uint4 basis_eval(float xv, float g0, float invh) {
    float e  = __expf(2.0f * xv);
    float xn = 1.0f - 2.0f / (e + 1.0f);   // tanh(xv)

    float t  = (xn - g0) * invh;
    int   m  = (int)floorf(t);
    m = min(max(m, 3), 7);
    float u  = t - (float)m;

    float um = 1.0f - u;
    float u2 = u * u, u3 = u2 * u;
    const float s = 1.0f / 6.0f;
    float w0 = um * um * um * s;
    float w1 = (3.0f * u3 - 6.0f * u2 + 4.0f) * s;
    float w2 = (-3.0f * u3 + 3.0f * u2 + 3.0f * u + 1.0f) * s;
    float w3 = u3 * s;
    int j0 = m - 3;                        // in [0,4]

    __half2 hA = __floats2half2_rn(w0, w1);
    __half2 hB = __floats2half2_rn(w2, w3);
    uint32_t u0 = *(uint32_t*)&hA;
    uint32_t u1 = *(uint32_t*)&hB;

    uint32_t b  = (j0 & 1) << 4;
    uint32_t t0 = u0 << b;
    uint32_t t1 = __funnelshift_l(u0, u1, b);
    uint32_t t2 = __funnelshift_l(u1, 0u, b);
    int ws = j0 >> 1;

    uint4 o;
    o.x = (ws == 0) ? t0 : 0u;
    o.y = (ws == 0) ? t1 : ((ws == 1) ? t0 : 0u);
    o.z = (ws == 0) ? t2 : ((ws == 1) ? t1 : t0);
    o.w = (ws == 1) ? t2 : ((ws == 2) ? t1 : 0u);
    return o;
}

__global__ void basis_kernel(const float* __restrict__ x,
                             const float* __restrict__ grid) {
    int p = blockIdx.x * blockDim.x + threadIdx.x;
    if (p >= M_ROWS * IN_F / 4) return;

    float g0   = __ldg(grid);
    float invh = 1.0f / (__ldg(grid + 1) - g0);

    float4 xv = reinterpret_cast<const float4*>(x)[p];
    uint4* dst = reinterpret_cast<uint4*>(g_Ah + (size_t)p * 32);
    // 4 independent evals: MUFU latency overlaps across them
    uint4 o0 = basis_eval(xv.x, g0, invh);
    uint4 o1 = basis_eval(xv.y, g0, invh);
    uint4 o2 = basis_eval(xv.z, g0, invh);
    uint4 o3 = basis_eval(xv.w, g0, invh);
    dst[0] = o0;
    dst[1] = o1;
    dst[2] = o2;
    dst[3] = o3;
}

// ---------------------------------------------------------------------------
// Kernel 2: pack W[o][i*8+k] = C[i][o][k], fp16.
// ---------------------------------------------------------------------------
__global__ void wpack_kernel(const float* __restrict__ coef) {
    int t = blockIdx.x * blockDim.x + threadIdx.x;
    if (t >= IN_F * OUT_F) return;
    int i = t & (IN_F - 1);
    int o = t >> 9;

    const float4* src = reinterpret_cast<const float4*>(coef + ((size_t)i * OUT_F + o) * 8);
    float4 c0 = __ldg(src);
    float4 c1 = __ldg(src + 1);

    __half2 h0 = __floats2half2_rn(c0.x, c0.y);
    __half2 h1 = __floats2half2_rn(c0.z, c0.w);
    __half2 h2 = __floats2half2_rn(c1.x, c1.y);
    __half2 h3 = __floats2half2_rn(c1.z, c1.w);
    *reinterpret_cast<uint4*>(g_Wh + (size_t)o * KDIM + i * 8) =
        make_uint4(*(uint32_t*)&h0, *(uint32_t*)&h1, *(uint32_t*)&h2, *(uint32_t*)&h3);
}

// ---------------------------------------------------------------------------
// Kernel 3: GEMM, mma.sync m16n8k16 fp16->fp32, ldmatrix, single barrier/chunk.
// CTA tile 224x128 (M padded to 8288), grid (4,37) = 148 CTAs = one wave.
// 8 warps 2x4, warp tile 112x32. 3-stage cp.async.
// ---------------------------------------------------------------------------
#define BM 224
#define BN 128
#define BK 32
#define ROWH 40                       // padded row (80B)
#define STAGES 3
#define KT (KDIM / BK)                // 128
#define A_ST (BM * ROWH)              // 8960 halves
#define B_ST (BN * ROWH)              // 5120 halves
#define SMEM_BYTES (STAGES * (A_ST + B_ST) * 2)   // 84480

__device__ __forceinline__ void cp16(void* smem, const void* gmem) {
    uint32_t sa = (uint32_t)__cvta_generic_to_shared(smem);
    asm volatile("cp.async.cg.shared.global [%0], [%1], 16;\n" :: "r"(sa), "l"(gmem));
}

__device__ __forceinline__ void ldsm_x4(uint32_t (&r)[4], uint32_t saddr) {
    asm volatile("ldmatrix.sync.aligned.m8n8.x4.shared.b16 {%0,%1,%2,%3}, [%4];"
                 : "=r"(r[0]), "=r"(r[1]), "=r"(r[2]), "=r"(r[3]) : "r"(saddr));
}

__device__ __forceinline__ void mma_f16(float (&d)[4], uint32_t a0, uint32_t a1,
                                        uint32_t a2, uint32_t a3,
                                        uint32_t b0, uint32_t b1) {
    asm volatile(
        "mma.sync.aligned.m16n8k16.row.col.f32.f16.f16.f32 "
        "{%0,%1,%2,%3}, {%4,%5,%6,%7}, {%8,%9}, {%0,%1,%2,%3};"
        : "+f"(d[0]), "+f"(d[1]), "+f"(d[2]), "+f"(d[3])
        : "r"(a0), "r"(a1), "r"(a2), "r"(a3), "r"(b0), "r"(b1));
}

__global__ void __launch_bounds__(256, 1) gemm_kernel(float* __restrict__ C) {
    extern __shared__ __half sm[];
    __half* AsBase = sm;
    __half* BsBase = sm + STAGES * A_ST;
    const uint32_t smem0 = (uint32_t)__cvta_generic_to_shared(sm);
    const uint32_t Bs0   = smem0 + STAGES * A_ST * 2;

    const int tid  = threadIdx.x;
    const int bm   = blockIdx.y * BM;
    const int bn   = blockIdx.x * BN;
    const int wid  = tid >> 5;
    const int lane = tid & 31;
    const int wm   = (wid >> 2) * 112;   // 0 / 112
    const int wn   = (wid & 3) * 32;     // 0..96
    const int gID  = lane >> 2;
    const int tg   = lane & 3;
    const int lrow = lane & 15;
    const int lcol = (lane >> 4) << 3;

    float acc[7][4][4];
#pragma unroll
    for (int a = 0; a < 7; ++a)
#pragma unroll
        for (int b = 0; b < 4; ++b)
#pragma unroll
            for (int c = 0; c < 4; ++c) acc[a][b][c] = 0.0f;

    auto issue = [&](int s, int kt) {
        int k0 = kt * BK;
        __half* As = AsBase + s * A_ST;
        __half* Bs = BsBase + s * B_ST;
#pragma unroll
        for (int i = 0; i < 4; ++i) {            // A: 224 rows x 4 chunks = 896
            int id = tid + 256 * i;
            if (id < BM * 4) {
                int r = id >> 2, c = id & 3;
                int gr = min(bm + r, M_ROWS - 1);
                cp16(As + r * ROWH + c * 8, g_Ah + (size_t)gr * KDIM + k0 + c * 8);
            }
        }
#pragma unroll
        for (int i = 0; i < 2; ++i) {            // B: 128 rows x 4 chunks = 512
            int id = tid + 256 * i;
            int r = id >> 2, c = id & 3;
            cp16(Bs + r * ROWH + c * 8, g_Wh + (size_t)(bn + r) * KDIM + k0 + c * 8);
        }
        asm volatile("cp.async.commit_group;\n");
    };

    issue(0, 0);
    issue(1, 1);

    for (int kt = 0; kt < KT; ++kt) {
        if (kt < KT - 1) {
            asm volatile("cp.async.wait_group 1;\n");
        } else {
            asm volatile("cp.async.wait_group 0;\n");
        }
        __syncthreads();   // single barrier per chunk: orders stage reuse safely

        if (kt + 2 < KT) issue((kt + 2) % STAGES, kt + 2);

        const int s = kt % STAGES;
        const uint32_t As_u = smem0 + (s * A_ST) * 2;
        const uint32_t Bs_u = Bs0 + (s * B_ST) * 2;

#pragma unroll
        for (int ks = 0; ks < BK; ks += 16) {
            uint32_t af[7][4];
#pragma unroll
            for (int mt = 0; mt < 7; ++mt)
                ldsm_x4(af[mt], As_u + ((wm + mt * 16 + lrow) * ROWH + ks + lcol) * 2);
            uint32_t bf[4][2];
#pragma unroll
            for (int j = 0; j < 2; ++j) {
                uint32_t r[4];
                ldsm_x4(r, Bs_u + ((wn + j * 16 + lrow) * ROWH + ks + lcol) * 2);
                bf[2 * j][0] = r[0]; bf[2 * j + 1][0] = r[1];
                bf[2 * j][1] = r[2]; bf[2 * j + 1][1] = r[3];
            }
#pragma unroll
            for (int mt = 0; mt < 7; ++mt)
#pragma unroll
                for (int nt = 0; nt < 4; ++nt)
                    mma_f16(acc[mt][nt], af[mt][0], af[mt][1], af[mt][2], af[mt][3],
                            bf[nt][0], bf[nt][1]);
        }
        // no trailing barrier: next iteration's top barrier provides ordering
    }

    // Epilogue: guarded fp32 stores (padded M rows skipped).
#pragma unroll
    for (int mt = 0; mt < 7; ++mt) {
        int r0 = bm + wm + mt * 16 + gID;
#pragma unroll
        for (int nt = 0; nt < 4; ++nt) {
            int c = bn + wn + nt * 8 + tg * 2;
            if (r0 < M_ROWS)
                *reinterpret_cast<float2*>(C + (size_t)r0 * OUT_F + c) =
                    make_float2(acc[mt][nt][0], acc[mt][nt][1]);
            if (r0 + 8 < M_ROWS)
                *reinterpret_cast<float2*>(C + (size_t)(r0 + 8) * OUT_F + c) =
                    make_float2(acc[mt][nt][2], acc[mt][nt][3]);
        }
    }
}

// ---------------------------------------------------------------------------
extern "C" void kernel_launch(void* const* d_in, const int* in_sizes, int n_in,
                              void* d_out, int out_size) {
    const float* x    = (const float*)d_in[0];
    const float* coef = (const float*)d_in[1];
    const float* grid = (const float*)d_in[2];
    float* out = (float*)d_out;

    basis_kernel<<<(M_ROWS * IN_F / 4 + 255) / 256, 256>>>(x, grid);
    wpack_kernel<<<(IN_F * OUT_F + 255) / 256, 256>>>(coef);

    static int smem_set = 0;
    if (!smem_set) {
        cudaFuncSetAttribute(gemm_kernel, cudaFuncAttributeMaxDynamicSharedMemorySize,
                             SMEM_BYTES);
        smem_set = 1;
    }
    dim3 g(OUT_F / BN, 37);   // 4 x 37 = 148 CTAs = one full wave
    gemm_kernel<<<g, 256, SMEM_BYTES>>>(out);
}

// round 10
// speedup vs baseline: 4.7288x; 1.1586x over previous
#include <cuda_runtime.h>
#include <cuda_fp16.h>
#include <cstdint>

// Problem sizes (fixed by the reference)
#define M_ROWS 8192
#define IN_F   512
#define OUT_F  512
#define KDIM   (IN_F * 8)   // 4096

// ---------------------------------------------------------------------------
// Device scratch (allocation-free rule: __device__ globals)
// ---------------------------------------------------------------------------
__device__ __align__(16) __half g_Ah[(size_t)M_ROWS * KDIM]; // 64 MB bases (fp16)
__device__ __align__(16) __half g_Wh[(size_t)OUT_F * KDIM];  //  4 MB packed coeffs

// ---------------------------------------------------------------------------
// Kernel 1: bases, 1 element/thread (best measured variant: R5, 20.4us).
// ---------------------------------------------------------------------------
__global__ void basis_kernel(const float* __restrict__ x,
                             const float* __restrict__ grid) {
    int idx = blockIdx.x * blockDim.x + threadIdx.x;
    if (idx >= M_ROWS * IN_F) return;

    float g0   = __ldg(grid);
    float invh = 1.0f / (__ldg(grid + 1) - g0);

    float xv = x[idx];
    float e  = __expf(2.0f * xv);
    float xn = 1.0f - 2.0f / (e + 1.0f);   // tanh(xv)

    float t  = (xn - g0) * invh;
    int   m  = (int)floorf(t);
    m = min(max(m, 3), 7);
    float u  = t - (float)m;

    float um = 1.0f - u;
    float u2 = u * u, u3 = u2 * u;
    const float s = 1.0f / 6.0f;
    float w0 = um * um * um * s;
    float w1 = (3.0f * u3 - 6.0f * u2 + 4.0f) * s;
    float w2 = (-3.0f * u3 + 3.0f * u2 + 3.0f * u + 1.0f) * s;
    float w3 = u3 * s;
    int j0 = m - 3;                        // in [0,4]

    __half2 hA = __floats2half2_rn(w0, w1);
    __half2 hB = __floats2half2_rn(w2, w3);
    uint32_t u0 = *(uint32_t*)&hA;
    uint32_t u1 = *(uint32_t*)&hB;

    uint32_t b  = (j0 & 1) << 4;
    uint32_t t0 = u0 << b;
    uint32_t t1 = __funnelshift_l(u0, u1, b);
    uint32_t t2 = __funnelshift_l(u1, 0u, b);
    int ws = j0 >> 1;

    uint32_t o0 = (ws == 0) ? t0 : 0u;
    uint32_t o1 = (ws == 0) ? t1 : ((ws == 1) ? t0 : 0u);
    uint32_t o2 = (ws == 0) ? t2 : ((ws == 1) ? t1 : t0);
    uint32_t o3 = (ws == 1) ? t2 : ((ws == 2) ? t1 : 0u);

    *reinterpret_cast<uint4*>(g_Ah + (size_t)idx * 8) = make_uint4(o0, o1, o2, o3);
}

// ---------------------------------------------------------------------------
// Kernel 2: pack W[o][i*8+k] = C[i][o][k], fp16.
// ---------------------------------------------------------------------------
__global__ void wpack_kernel(const float* __restrict__ coef) {
    int t = blockIdx.x * blockDim.x + threadIdx.x;
    if (t >= IN_F * OUT_F) return;
    int i = t & (IN_F - 1);
    int o = t >> 9;

    const float4* src = reinterpret_cast<const float4*>(coef + ((size_t)i * OUT_F + o) * 8);
    float4 c0 = __ldg(src);
    float4 c1 = __ldg(src + 1);

    __half2 h0 = __floats2half2_rn(c0.x, c0.y);
    __half2 h1 = __floats2half2_rn(c0.z, c0.w);
    __half2 h2 = __floats2half2_rn(c1.x, c1.y);
    __half2 h3 = __floats2half2_rn(c1.z, c1.w);
    *reinterpret_cast<uint4*>(g_Wh + (size_t)o * KDIM + i * 8) =
        make_uint4(*(uint32_t*)&h0, *(uint32_t*)&h1, *(uint32_t*)&h2, *(uint32_t*)&h3);
}

// ---------------------------------------------------------------------------
// Kernel 3: GEMM, mma.sync m16n8k16 fp16->fp32, ldmatrix.
// CTA tile 224x128 (M padded to 8288), grid (4,37) = 148 CTAs = one wave.
// 8 warps 2x4, warp tile 112x32. BK=64 (half the barriers), 3-stage cp.async,
// single barrier per chunk.
// ---------------------------------------------------------------------------
#define BM 224
#define BN 128
#define BK 64                         // halves per K chunk
#define ROWH 72                       // padded row stride (144B): LDSM conflict-free
#define STAGES 3
#define KT (KDIM / BK)                // 64
#define A_ST (BM * ROWH)              // 16128 halves
#define B_ST (BN * ROWH)              //  9216 halves
#define SMEM_BYTES (STAGES * (A_ST + B_ST) * 2)   // 152064

__device__ __forceinline__ void cp16(void* smem, const void* gmem) {
    uint32_t sa = (uint32_t)__cvta_generic_to_shared(smem);
    asm volatile("cp.async.cg.shared.global [%0], [%1], 16;\n" :: "r"(sa), "l"(gmem));
}

__device__ __forceinline__ void ldsm_x4(uint32_t (&r)[4], uint32_t saddr) {
    asm volatile("ldmatrix.sync.aligned.m8n8.x4.shared.b16 {%0,%1,%2,%3}, [%4];"
                 : "=r"(r[0]), "=r"(r[1]), "=r"(r[2]), "=r"(r[3]) : "r"(saddr));
}

__device__ __forceinline__ void mma_f16(float (&d)[4], uint32_t a0, uint32_t a1,
                                        uint32_t a2, uint32_t a3,
                                        uint32_t b0, uint32_t b1) {
    asm volatile(
        "mma.sync.aligned.m16n8k16.row.col.f32.f16.f16.f32 "
        "{%0,%1,%2,%3}, {%4,%5,%6,%7}, {%8,%9}, {%0,%1,%2,%3};"
        : "+f"(d[0]), "+f"(d[1]), "+f"(d[2]), "+f"(d[3])
        : "r"(a0), "r"(a1), "r"(a2), "r"(a3), "r"(b0), "r"(b1));
}

__global__ void __launch_bounds__(256, 1) gemm_kernel(float* __restrict__ C) {
    extern __shared__ __half sm[];
    __half* AsBase = sm;
    __half* BsBase = sm + STAGES * A_ST;
    const uint32_t smem0 = (uint32_t)__cvta_generic_to_shared(sm);
    const uint32_t Bs0   = smem0 + STAGES * A_ST * 2;

    const int tid  = threadIdx.x;
    const int bm   = blockIdx.y * BM;
    const int bn   = blockIdx.x * BN;
    const int wid  = tid >> 5;
    const int lane = tid & 31;
    const int wm   = (wid >> 2) * 112;   // 0 / 112
    const int wn   = (wid & 3) * 32;     // 0..96
    const int gID  = lane >> 2;
    const int tg   = lane & 3;
    const int lrow = lane & 15;
    const int lcol = (lane >> 4) << 3;

    float acc[7][4][4];
#pragma unroll
    for (int a = 0; a < 7; ++a)
#pragma unroll
        for (int b = 0; b < 4; ++b)
#pragma unroll
            for (int c = 0; c < 4; ++c) acc[a][b][c] = 0.0f;

    auto issue = [&](int s, int kt) {
        int k0 = kt * BK;
        __half* As = AsBase + s * A_ST;
        __half* Bs = BsBase + s * B_ST;
#pragma unroll
        for (int i = 0; i < 7; ++i) {            // A: 224 rows x 8 chunks = 1792
            int id = tid + 256 * i;
            int r = id >> 3, c = id & 7;
            int gr = min(bm + r, M_ROWS - 1);
            cp16(As + r * ROWH + c * 8, g_Ah + (size_t)gr * KDIM + k0 + c * 8);
        }
#pragma unroll
        for (int i = 0; i < 4; ++i) {            // B: 128 rows x 8 chunks = 1024
            int id = tid + 256 * i;
            int r = id >> 3, c = id & 7;
            cp16(Bs + r * ROWH + c * 8, g_Wh + (size_t)(bn + r) * KDIM + k0 + c * 8);
        }
        asm volatile("cp.async.commit_group;\n");
    };

    issue(0, 0);
    issue(1, 1);

    for (int kt = 0; kt < KT; ++kt) {
        if (kt < KT - 1) {
            asm volatile("cp.async.wait_group 1;\n");
        } else {
            asm volatile("cp.async.wait_group 0;\n");
        }
        __syncthreads();   // single barrier per chunk

        if (kt + 2 < KT) issue((kt + 2) % STAGES, kt + 2);

        const int s = kt % STAGES;
        const uint32_t As_u = smem0 + (s * A_ST) * 2;
        const uint32_t Bs_u = Bs0 + (s * B_ST) * 2;

#pragma unroll
        for (int ks = 0; ks < BK; ks += 16) {
            uint32_t af[7][4];
#pragma unroll
            for (int mt = 0; mt < 7; ++mt)
                ldsm_x4(af[mt], As_u + ((wm + mt * 16 + lrow) * ROWH + ks + lcol) * 2);
            uint32_t bf[4][2];
#pragma unroll
            for (int j = 0; j < 2; ++j) {
                uint32_t r[4];
                ldsm_x4(r, Bs_u + ((wn + j * 16 + lrow) * ROWH + ks + lcol) * 2);
                bf[2 * j][0] = r[0]; bf[2 * j + 1][0] = r[1];
                bf[2 * j][1] = r[2]; bf[2 * j + 1][1] = r[3];
            }
#pragma unroll
            for (int mt = 0; mt < 7; ++mt)
#pragma unroll
                for (int nt = 0; nt < 4; ++nt)
                    mma_f16(acc[mt][nt], af[mt][0], af[mt][1], af[mt][2], af[mt][3],
                            bf[nt][0], bf[nt][1]);
        }
        // no trailing barrier: next iteration's top barrier orders stage reuse
    }

    // Epilogue: guarded fp32 stores (padded M rows skipped).
#pragma unroll
    for (int mt = 0; mt < 7; ++mt) {
        int r0 = bm + wm + mt * 16 + gID;
#pragma unroll
        for (int nt = 0; nt < 4; ++nt) {
            int c = bn + wn + nt * 8 + tg * 2;
            if (r0 < M_ROWS)
                *reinterpret_cast<float2*>(C + (size_t)r0 * OUT_F + c) =
                    make_float2(acc[mt][nt][0], acc[mt][nt][1]);
            if (r0 + 8 < M_ROWS)
                *reinterpret_cast<float2*>(C + (size_t)(r0 + 8) * OUT_F + c) =
                    make_float2(acc[mt][nt][2], acc[mt][nt][3]);
        }
    }
}

// ---------------------------------------------------------------------------
extern "C" void kernel_launch(void* const* d_in, const int* in_sizes, int n_in,
                              void* d_out, int out_size) {
    const float* x    = (const float*)d_in[0];
    const float* coef = (const float*)d_in[1];
    const float* grid = (const float*)d_in[2];
    float* out = (float*)d_out;

    basis_kernel<<<(M_ROWS * IN_F + 255) / 256, 256>>>(x, grid);
    wpack_kernel<<<(IN_F * OUT_F + 255) / 256, 256>>>(coef);

    static int smem_set = 0;
    if (!smem_set) {
        cudaFuncSetAttribute(gemm_kernel, cudaFuncAttributeMaxDynamicSharedMemorySize,
                             SMEM_BYTES);
        smem_set = 1;
    }
    dim3 g(OUT_F / BN, 37);   // 4 x 37 = 148 CTAs = one full wave
    gemm_kernel<<<g, 256, SMEM_BYTES>>>(out);
}